// round 1
// baseline (speedup 1.0000x reference)
#include <cuda_runtime.h>
#include <cstddef>

// Problem constants
#define HH 256
#define WW 256
#define BB 16
#define CC 64
#define LL 256
#define HW 65536

// ---------------- scratch (device globals; no allocation allowed) ----------
__device__ float  g_bufA[(size_t)BB * CC * HW];   // 268 MB
__device__ float  g_bufB[(size_t)BB * CC * HW];   // 268 MB
__device__ float2 g_G[(size_t)BB * HH * 21];      // per-row column-DFT at 21 freqs
__device__ float2 g_delta[BB * LL];
__device__ float2 g_U[(size_t)BB * 21 * WW];
__device__ float  g_T[BB * CC * 9];               // msg contribution, 9 border cases
__device__ int    g_dy[LL];
__device__ int    g_dx[LL];

// ---------------- watermark index generation (matches reference order) -----
__global__ void gen_indices() {
    int n = 0;
    for (int i = -10; i <= 10; i++) {
        for (int j = -10; j <= 10; j++) {
            if (i * i + j * j <= 100 && n < LL) {
                g_dy[n] = i;
                g_dx[n] = j;
                n++;
            }
        }
    }
}

// ---------------- generic conv3x3 + BN + ReLU ------------------------------
// tile: 32 (w) x 8 (h), 128 threads: 4 groups of 32 lanes; each thread holds
// 16 out-channels x 8 rows of fp32 accumulators.
__global__ void __launch_bounds__(128, 2)
conv3x3(const float* __restrict__ in, int CI,
        const float* __restrict__ wt,
        const float* __restrict__ bb, const float* __restrict__ gg,
        const float* __restrict__ bee, const float* __restrict__ mm,
        const float* __restrict__ vv,
        float* __restrict__ out)
{
    const int w0 = blockIdx.x * 32, h0 = blockIdx.y * 8, b = blockIdx.z;
    const int tid = threadIdx.x, lane = tid & 31, og = tid >> 5;
    const int obase = og * 16;

    __shared__ float s_in[10 * 34];
    __shared__ float s_w[64 * 9];

    float acc[16][8];
#pragma unroll
    for (int o = 0; o < 16; o++)
#pragma unroll
        for (int px = 0; px < 8; px++) acc[o][px] = 0.f;

    for (int c = 0; c < CI; c++) {
        __syncthreads();
        const float* ip = in + (size_t)(b * CI + c) * HW;
        for (int idx = tid; idx < 340; idx += 128) {
            int r = idx / 34, cc2 = idx - r * 34;
            int gy = h0 - 1 + r, gx = w0 - 1 + cc2;
            s_in[idx] = (gy >= 0 && gy < HH && gx >= 0 && gx < WW)
                            ? ip[gy * WW + gx] : 0.f;
        }
        const float* wp = wt + (size_t)c * 9;
        for (int idx = tid; idx < 576; idx += 128) {
            int o = idx / 9, k = idx - o * 9;
            s_w[idx] = wp[(size_t)o * CI * 9 + k];
        }
        __syncthreads();

        float p[10][3];
#pragma unroll
        for (int r = 0; r < 10; r++) {
            p[r][0] = s_in[r * 34 + lane];
            p[r][1] = s_in[r * 34 + lane + 1];
            p[r][2] = s_in[r * 34 + lane + 2];
        }
#pragma unroll
        for (int o = 0; o < 16; o++) {
            const float* ws = &s_w[(obase + o) * 9];
            float q0 = ws[0], q1 = ws[1], q2 = ws[2];
            float q3 = ws[3], q4 = ws[4], q5 = ws[5];
            float q6 = ws[6], q7 = ws[7], q8 = ws[8];
#pragma unroll
            for (int px = 0; px < 8; px++) {
                float a = acc[o][px];
                a = fmaf(q0, p[px][0], a);
                a = fmaf(q1, p[px][1], a);
                a = fmaf(q2, p[px][2], a);
                a = fmaf(q3, p[px + 1][0], a);
                a = fmaf(q4, p[px + 1][1], a);
                a = fmaf(q5, p[px + 1][2], a);
                a = fmaf(q6, p[px + 2][0], a);
                a = fmaf(q7, p[px + 2][1], a);
                a = fmaf(q8, p[px + 2][2], a);
                acc[o][px] = a;
            }
        }
    }

#pragma unroll
    for (int o = 0; o < 16; o++) {
        int oc = obase + o;
        float s = gg[oc] * rsqrtf(vv[oc] + 1e-5f);
        float t = fmaf(s, bb[oc] - mm[oc], bee[oc]);
#pragma unroll
        for (int px = 0; px < 8; px++) {
            float r = fmaxf(fmaf(s, acc[o][px], t), 0.f);
            out[((size_t)(b * CC + oc) * HH + (h0 + px)) * WW + w0 + lane] = r;
        }
    }
}

// ---------------- wa conv: 67 effective channels (64 enc + 3 image) --------
// message-channel contribution is the precomputed constant g_T (9 pad cases).
__global__ void __launch_bounds__(128, 2)
conv_wa(const float* __restrict__ enc, const float* __restrict__ img,
        const float* __restrict__ wt,
        const float* __restrict__ bb, const float* __restrict__ gg,
        const float* __restrict__ bee, const float* __restrict__ mm,
        const float* __restrict__ vv,
        float* __restrict__ out)
{
    const int w0 = blockIdx.x * 32, h0 = blockIdx.y * 8, b = blockIdx.z;
    const int tid = threadIdx.x, lane = tid & 31, og = tid >> 5;
    const int obase = og * 16;

    __shared__ float s_in[10 * 34];
    __shared__ float s_w[64 * 9];
    __shared__ float s_T[64 * 9];

    for (int idx = tid; idx < 576; idx += 128)
        s_T[idx] = g_T[(size_t)b * 576 + idx];
    __syncthreads();

    const int wglob = w0 + lane;
    const int cxl = (wglob == 0) ? 0 : ((wglob == WW - 1) ? 2 : 1);

    float acc[16][8];
#pragma unroll
    for (int o = 0; o < 16; o++)
#pragma unroll
        for (int px = 0; px < 8; px++) {
            int h = h0 + px;
            int cy = (h == 0) ? 0 : ((h == HH - 1) ? 2 : 1);
            acc[o][px] = s_T[(obase + o) * 9 + cy * 3 + cxl];
        }

    for (int c = 0; c < 67; c++) {
        __syncthreads();
        const float* ip;
        int cin;
        if (c < 64) { ip = enc + (size_t)(b * CC + c) * HW; cin = 256 + c; }
        else        { ip = img + (size_t)(b * 3 + (c - 64)) * HW; cin = 320 + (c - 64); }

        for (int idx = tid; idx < 340; idx += 128) {
            int r = idx / 34, cc2 = idx - r * 34;
            int gy = h0 - 1 + r, gx = w0 - 1 + cc2;
            s_in[idx] = (gy >= 0 && gy < HH && gx >= 0 && gx < WW)
                            ? ip[gy * WW + gx] : 0.f;
        }
        for (int idx = tid; idx < 576; idx += 128) {
            int o = idx / 9, k = idx - o * 9;
            s_w[idx] = wt[((size_t)o * 323 + cin) * 9 + k];
        }
        __syncthreads();

        float p[10][3];
#pragma unroll
        for (int r = 0; r < 10; r++) {
            p[r][0] = s_in[r * 34 + lane];
            p[r][1] = s_in[r * 34 + lane + 1];
            p[r][2] = s_in[r * 34 + lane + 2];
        }
#pragma unroll
        for (int o = 0; o < 16; o++) {
            const float* ws = &s_w[(obase + o) * 9];
            float q0 = ws[0], q1 = ws[1], q2 = ws[2];
            float q3 = ws[3], q4 = ws[4], q5 = ws[5];
            float q6 = ws[6], q7 = ws[7], q8 = ws[8];
#pragma unroll
            for (int px = 0; px < 8; px++) {
                float a = acc[o][px];
                a = fmaf(q0, p[px][0], a);
                a = fmaf(q1, p[px][1], a);
                a = fmaf(q2, p[px][2], a);
                a = fmaf(q3, p[px + 1][0], a);
                a = fmaf(q4, p[px + 1][1], a);
                a = fmaf(q5, p[px + 1][2], a);
                a = fmaf(q6, p[px + 2][0], a);
                a = fmaf(q7, p[px + 2][1], a);
                a = fmaf(q8, p[px + 2][2], a);
                acc[o][px] = a;
            }
        }
    }

#pragma unroll
    for (int o = 0; o < 16; o++) {
        int oc = obase + o;
        float s = gg[oc] * rsqrtf(vv[oc] + 1e-5f);
        float t = fmaf(s, bb[oc] - mm[oc], bee[oc]);
#pragma unroll
        for (int px = 0; px < 8; px++) {
            float r = fmaxf(fmaf(s, acc[o][px], t), 0.f);
            out[((size_t)(b * CC + oc) * HH + (h0 + px)) * WW + w0 + lane] = r;
        }
    }
}

// ---------------- msg contribution T[b][o][case] ---------------------------
__global__ void msgT(const float* __restrict__ msg, const float* __restrict__ wa)
{
    int o = blockIdx.x, b = blockIdx.y, l = threadIdx.x;
    __shared__ float S[9][256];
    float m = msg[b * LL + l];
    const float* wp = wa + ((size_t)o * 323 + l) * 9;
#pragma unroll
    for (int k = 0; k < 9; k++) S[k][l] = m * wp[k];
    __syncthreads();
    for (int s = 128; s > 0; s >>= 1) {
        if (l < s) {
#pragma unroll
            for (int k = 0; k < 9; k++) S[k][l] += S[k][l + s];
        }
        __syncthreads();
    }
    if (l == 0) {
        float P[9];
#pragma unroll
        for (int k = 0; k < 9; k++) P[k] = S[k][0];
        for (int cy = 0; cy < 3; cy++) {
            for (int cx = 0; cx < 3; cx++) {
                float t = 0.f;
                for (int ky = 0; ky < 3; ky++) {
                    if (!(cy == 1 || (cy == 0 && ky >= 1) || (cy == 2 && ky <= 1))) continue;
                    for (int kx = 0; kx < 3; kx++) {
                        if (!(cx == 1 || (cx == 0 && kx >= 1) || (cx == 2 && kx <= 1))) continue;
                        t += P[ky * 3 + kx];
                    }
                }
                g_T[((size_t)b * CC + o) * 9 + cy * 3 + cx] = t;
            }
        }
    }
}

// ---------------- watermark: sparse-frequency fft edit ---------------------
// K1: G[b,h,j] = sum_w x0[b,h,w] * exp(-2*pi*i * (118+j) * w / 256)
__global__ void kG(const float* __restrict__ x)
{
    int h = blockIdx.x, b = blockIdx.y, lane = threadIdx.x;
    __shared__ float ct[256], st[256];
    for (int i = lane; i < 256; i += 32) {
        float s, c;
        sincosf(6.283185307179586f * (float)i / 256.f, &s, &c);
        ct[i] = c; st[i] = s;
    }
    __syncthreads();
    const float* xp = x + ((size_t)(b * CC) * HH + h) * WW;
    float gr[21], gi[21];
#pragma unroll
    for (int j = 0; j < 21; j++) { gr[j] = 0.f; gi[j] = 0.f; }
    for (int w = lane; w < WW; w += 32) {
        float v = xp[w];
#pragma unroll
        for (int j = 0; j < 21; j++) {
            int idx = ((118 + j) * w) & 255;
            gr[j] = fmaf(v, ct[idx], gr[j]);
            gi[j] = fmaf(-v, st[idx], gi[j]);
        }
    }
#pragma unroll
    for (int j = 0; j < 21; j++) {
        for (int off = 16; off; off >>= 1) {
            gr[j] += __shfl_down_sync(0xffffffffu, gr[j], off);
            gi[j] += __shfl_down_sync(0xffffffffu, gi[j], off);
        }
    }
    if (lane == 0) {
#pragma unroll
        for (int j = 0; j < 21; j++)
            g_G[((size_t)b * HH + h) * 21 + j] = make_float2(gr[j], gi[j]);
    }
}

// K2: F[b,l] then delta[b,l] = (m + i m) - F
__global__ void kF(const float* __restrict__ msg)
{
    int b = blockIdx.x, l = threadIdx.x;
    __shared__ float ct[256], st[256];
    {
        float s, c;
        sincosf(6.283185307179586f * (float)l / 256.f, &s, &c);
        ct[l] = c; st[l] = s;
    }
    __syncthreads();
    int dy = g_dy[l], dx = g_dx[l];
    int jx = dx + 10, yy = 128 + dy;
    float fr = 0.f, fi = 0.f;
    for (int h = 0; h < HH; h++) {
        float2 G = g_G[((size_t)b * HH + h) * 21 + jx];
        int idx = (yy * h) & 255;
        float c = ct[idx], s = st[idx];
        fr += G.x * c + G.y * s;
        fi += G.y * c - G.x * s;
    }
    float m = msg[b * LL + l];
    g_delta[b * LL + l] = make_float2(m - fr, m - fi);
}

// K3: U[b,iy,w] = sum_{l: dy_l+10 == iy} delta[b,l] * exp(+2*pi*i*(128+dx_l)*w/256)
__global__ void kU()
{
    int iy = blockIdx.x, b = blockIdx.y, w = threadIdx.x;
    __shared__ float ct[256], st[256], dr[256], di[256];
    __shared__ int sdx[256], sdy[256];
    {
        float s, c;
        sincosf(6.283185307179586f * (float)w / 256.f, &s, &c);
        ct[w] = c; st[w] = s;
        float2 d = g_delta[b * LL + w];
        dr[w] = d.x; di[w] = d.y;
        sdx[w] = g_dx[w]; sdy[w] = g_dy[w];
    }
    __syncthreads();
    float ur = 0.f, ui = 0.f;
    for (int l = 0; l < LL; l++) {
        if (sdy[l] + 10 == iy) {
            int idx = ((128 + sdx[l]) * w) & 255;
            float c = ct[idx], s = st[idx];
            ur += dr[l] * c - di[l] * s;
            ui += dr[l] * s + di[l] * c;
        }
    }
    g_U[((size_t)b * 21 + iy) * WW + w] = make_float2(ur, ui);
}

// K4: x[b,0,h,w] += (1/65536) * Re( sum_iy U[b,iy,w] * exp(+2*pi*i*(118+iy)*h/256) )
__global__ void kAdd(float* __restrict__ x)
{
    int h = blockIdx.x, b = blockIdx.y, w = threadIdx.x;
    __shared__ float ct[256], st[256];
    {
        float s, c;
        sincosf(6.283185307179586f * (float)w / 256.f, &s, &c);
        ct[w] = c; st[w] = s;
    }
    __syncthreads();
    float a = 0.f;
#pragma unroll
    for (int iy = 0; iy < 21; iy++) {
        int idx = ((118 + iy) * h) & 255;
        float2 U = g_U[((size_t)b * 21 + iy) * WW + w];
        a += U.x * ct[idx] - U.y * st[idx];
    }
    size_t off = ((size_t)(b * CC) * HH + h) * WW + w;
    x[off] += a * (1.f / 65536.f);
}

// ---------------- final 1x1 projection 64 -> 3 -----------------------------
__global__ void final1x1(const float* __restrict__ y, const float* __restrict__ wf,
                         const float* __restrict__ bf, float* __restrict__ out)
{
    int w = threadIdx.x, h = blockIdx.x, b = blockIdx.y;
    __shared__ float swf[192];
    __shared__ float sbf[3];
    if (threadIdx.x < 192) swf[threadIdx.x] = wf[threadIdx.x];
    if (threadIdx.x < 3) sbf[threadIdx.x] = bf[threadIdx.x];
    __syncthreads();
    float a0 = sbf[0], a1 = sbf[1], a2 = sbf[2];
    const float* yp = y + ((size_t)(b * CC) * HH + h) * WW + w;
#pragma unroll 8
    for (int c = 0; c < 64; c++) {
        float v = yp[(size_t)c * HW];
        a0 = fmaf(v, swf[c], a0);
        a1 = fmaf(v, swf[64 + c], a1);
        a2 = fmaf(v, swf[128 + c], a2);
    }
    size_t o = ((size_t)(b * 3) * HH + h) * WW + w;
    out[o] = a0;
    out[o + (size_t)HW] = a1;
    out[o + (size_t)2 * HW] = a2;
}

// ---------------- launcher -------------------------------------------------
extern "C" void kernel_launch(void* const* d_in, const int* in_sizes, int n_in,
                              void* d_out, int out_size)
{
    const float* image   = (const float*)d_in[0];
    const float* message = (const float*)d_in[1];
    const float* w0  = (const float*)d_in[2];
    const float* b0  = (const float*)d_in[3];
    const float* g0  = (const float*)d_in[4];
    const float* be0 = (const float*)d_in[5];
    const float* m0  = (const float*)d_in[6];
    const float* v0  = (const float*)d_in[7];
    const float* wk  = (const float*)d_in[8];
    const float* bk  = (const float*)d_in[9];
    const float* gk  = (const float*)d_in[10];
    const float* bek = (const float*)d_in[11];
    const float* mk  = (const float*)d_in[12];
    const float* vk  = (const float*)d_in[13];
    const float* wa  = (const float*)d_in[14];
    const float* ba  = (const float*)d_in[15];
    const float* ga  = (const float*)d_in[16];
    const float* bea = (const float*)d_in[17];
    const float* ma  = (const float*)d_in[18];
    const float* va  = (const float*)d_in[19];
    const float* wf  = (const float*)d_in[20];
    const float* bf  = (const float*)d_in[21];

    float* bufA = nullptr;
    float* bufB = nullptr;
    cudaGetSymbolAddress((void**)&bufA, g_bufA);
    cudaGetSymbolAddress((void**)&bufB, g_bufB);

    dim3 cgrid(WW / 32, HH / 8, BB);
    const size_t WKS = (size_t)64 * 64 * 9;

    gen_indices<<<1, 1>>>();

    conv3x3<<<cgrid, 128>>>(image, 3, w0, b0, g0, be0, m0, v0, bufA);
    conv3x3<<<cgrid, 128>>>(bufA, 64, wk,            bk,       gk,       bek,       mk,       vk,       bufB);
    conv3x3<<<cgrid, 128>>>(bufB, 64, wk + WKS,      bk + 64,  gk + 64,  bek + 64,  mk + 64,  vk + 64,  bufA);
    conv3x3<<<cgrid, 128>>>(bufA, 64, wk + 2 * WKS,  bk + 128, gk + 128, bek + 128, mk + 128, vk + 128, bufB);

    // watermark (modifies channel 0 of bufB in place)
    kG<<<dim3(HH, BB), 32>>>(bufB);
    kF<<<BB, 256>>>(message);
    kU<<<dim3(21, BB), 256>>>();
    kAdd<<<dim3(HH, BB), 256>>>(bufB);

    // message-channel contribution to wa conv
    msgT<<<dim3(64, BB), 256>>>(message, wa);

    conv_wa<<<cgrid, 128>>>(bufB, image, wa, ba, ga, bea, ma, va, bufA);

    final1x1<<<dim3(HH, BB), 256>>>(bufA, wf, bf, (float*)d_out);
}

// round 2
// speedup vs baseline: 1.6439x; 1.6439x over previous
#include <cuda_runtime.h>
#include <cstddef>

// Problem constants
#define HH 256
#define WW 256
#define BB 16
#define CC 64
#define LL 256
#define HW 65536

// ---------------- scratch (device globals; no allocation allowed) ----------
__device__ float  g_bufA[(size_t)BB * CC * HW];   // 268 MB
__device__ float  g_bufB[(size_t)BB * CC * HW];   // 268 MB
__device__ float2 g_G[(size_t)BB * HH * 21];
__device__ float2 g_delta[BB * LL];
__device__ float2 g_U[(size_t)BB * 21 * WW];
__device__ float  g_T[BB * CC * 9];
__device__ int    g_dy[LL];
__device__ int    g_dx[LL];
// transposed weights: [c][o*9+k] per layer, packed back-to-back
// layer0: 3ch @0 ; layers1-3: 64ch @1728, 38592, 75456 ; wa: 67ch @112320
__device__ float  g_wT[150912];

#define WT_O0 0
#define WT_O1 1728
#define WT_O2 38592
#define WT_O3 75456
#define WT_O4 112320

// ---------------- f32x2 helpers --------------------------------------------
__device__ __forceinline__ unsigned long long pk2(float lo, float hi) {
    unsigned long long r;
    asm("mov.b64 %0, {%1,%2};" : "=l"(r) : "f"(lo), "f"(hi));
    return r;
}
__device__ __forceinline__ void upk2(unsigned long long v, float& lo, float& hi) {
    asm("mov.b64 {%0,%1}, %2;" : "=f"(lo), "=f"(hi) : "l"(v));
}
__device__ __forceinline__ void ffma2(unsigned long long& d,
                                      unsigned long long a, unsigned long long b) {
    asm("fma.rn.f32x2 %0, %1, %2, %0;" : "+l"(d) : "l"(a), "l"(b));
}

// ---------------- watermark index generation -------------------------------
__global__ void gen_indices() {
    int n = 0;
    for (int i = -10; i <= 10; i++)
        for (int j = -10; j <= 10; j++)
            if (i * i + j * j <= 100 && n < LL) { g_dy[n] = i; g_dx[n] = j; n++; }
}

// ---------------- weight transpose: wT[c][o*9+k] = w[o][cbase+c][k] --------
__global__ void xposeW(const float* __restrict__ w, int CItot, int cbase, int nc,
                       float* __restrict__ outw) {
    int idx = blockIdx.x * 256 + threadIdx.x;
    if (idx >= nc * 576) return;
    int c = idx / 576, r = idx - c * 576, o = r / 9, k = r - o * 9;
    outw[idx] = w[((size_t)o * CItot + cbase + c) * 9 + k];
}

// ---------------- conv3x3 + BN + ReLU (FFMA2, double-buffered) -------------
// 256 threads = 8 groups x 32 lanes; tile 32(w) x 8(h); each thread: 8 oc,
// 4 row-pairs of f32x2 accumulators.
__global__ void __launch_bounds__(256, 2)
conv3x3(const float* __restrict__ in, int CI, const float* __restrict__ wT,
        const float* __restrict__ bb, const float* __restrict__ gg,
        const float* __restrict__ bee, const float* __restrict__ mm,
        const float* __restrict__ vv, float* __restrict__ out)
{
    const int w0 = blockIdx.x * 32, h0 = blockIdx.y * 8, b = blockIdx.z;
    const int tid = threadIdx.x, lane = tid & 31, og = tid >> 5;
    const int obase = og * 8;

    __shared__ float s_in[2][10 * 34];
    __shared__ float s_w[2][576];

    // preload channel 0
    {
        const float* ip = in + (size_t)(b * CI) * HW;
        for (int idx = tid; idx < 340; idx += 256) {
            int r = idx / 34, cc2 = idx - r * 34;
            int gy = h0 - 1 + r, gx = w0 - 1 + cc2;
            s_in[0][idx] = (gy >= 0 && gy < HH && gx >= 0 && gx < WW)
                               ? ip[gy * WW + gx] : 0.f;
        }
        for (int idx = tid; idx < 576; idx += 256) s_w[0][idx] = wT[idx];
    }
    __syncthreads();

    unsigned long long acc2[8][4];
#pragma unroll
    for (int o = 0; o < 8; o++)
#pragma unroll
        for (int m = 0; m < 4; m++) acc2[o][m] = 0ull;

    for (int c = 0; c < CI; c++) {
        const int cur = c & 1, nxt = cur ^ 1;
        const bool has = (c + 1 < CI);
        float tin0 = 0.f, tin1 = 0.f, tw0 = 0.f, tw1 = 0.f, tw2 = 0.f;
        if (has) {
            const float* ip = in + (size_t)(b * CI + c + 1) * HW;
            {
                int r = tid / 34, cc2 = tid - r * 34;
                int gy = h0 - 1 + r, gx = w0 - 1 + cc2;
                tin0 = (tid < 340 && gy >= 0 && gy < HH && gx >= 0 && gx < WW)
                           ? ip[gy * WW + gx] : 0.f;
            }
            if (tid < 84) {
                int idx = tid + 256;
                int r = idx / 34, cc2 = idx - r * 34;
                int gy = h0 - 1 + r, gx = w0 - 1 + cc2;
                tin1 = (gy >= 0 && gy < HH && gx >= 0 && gx < WW)
                           ? ip[gy * WW + gx] : 0.f;
            }
            const float* wp = wT + (size_t)(c + 1) * 576;
            tw0 = wp[tid];
            tw1 = wp[tid + 256];
            if (tid < 64) tw2 = wp[tid + 512];
        }

        // compute on s_in[cur]/s_w[cur]
        const float* si = s_in[cur];
#pragma unroll
        for (int ky = 0; ky < 3; ky++) {
            unsigned long long p2[4][3];
#pragma unroll
            for (int m = 0; m < 4; m++) {
                int r = ky + 2 * m;
#pragma unroll
                for (int k = 0; k < 3; k++)
                    p2[m][k] = pk2(si[r * 34 + lane + k],
                                   si[(r + 1) * 34 + lane + k]);
            }
#pragma unroll
            for (int o = 0; o < 8; o++) {
                const float* ws = &s_w[cur][(obase + o) * 9 + ky * 3];
#pragma unroll
                for (int kx = 0; kx < 3; kx++) {
                    float q = ws[kx];
                    unsigned long long q2 = pk2(q, q);
#pragma unroll
                    for (int m = 0; m < 4; m++) ffma2(acc2[o][m], q2, p2[m][kx]);
                }
            }
        }

        if (has) {
            if (tid < 340) s_in[nxt][tid] = tin0;
            if (tid < 84)  s_in[nxt][tid + 256] = tin1;
            s_w[nxt][tid] = tw0;
            s_w[nxt][tid + 256] = tw1;
            if (tid < 64) s_w[nxt][tid + 512] = tw2;
        }
        __syncthreads();
    }

#pragma unroll
    for (int o = 0; o < 8; o++) {
        int oc = obase + o;
        float s = gg[oc] * rsqrtf(vv[oc] + 1e-5f);
        float t = fmaf(s, bb[oc] - mm[oc], bee[oc]);
#pragma unroll
        for (int m = 0; m < 4; m++) {
            float lo, hi;
            upk2(acc2[o][m], lo, hi);
            float r0 = fmaxf(fmaf(s, lo, t), 0.f);
            float r1 = fmaxf(fmaf(s, hi, t), 0.f);
            size_t base = ((size_t)(b * CC + oc) * HH + (h0 + 2 * m)) * WW + w0 + lane;
            out[base] = r0;
            out[base + WW] = r1;
        }
    }
}

// ---------------- wa conv: 67 effective channels ---------------------------
__global__ void __launch_bounds__(256, 2)
conv_wa(const float* __restrict__ enc, const float* __restrict__ img,
        const float* __restrict__ wT,
        const float* __restrict__ bb, const float* __restrict__ gg,
        const float* __restrict__ bee, const float* __restrict__ mm,
        const float* __restrict__ vv, float* __restrict__ out)
{
    const int w0 = blockIdx.x * 32, h0 = blockIdx.y * 8, b = blockIdx.z;
    const int tid = threadIdx.x, lane = tid & 31, og = tid >> 5;
    const int obase = og * 8;

    __shared__ float s_in[2][10 * 34];
    __shared__ float s_w[2][576];
    __shared__ float s_T[64 * 9];

    for (int idx = tid; idx < 576; idx += 256)
        s_T[idx] = g_T[(size_t)b * 576 + idx];

    // preload channel 0 (enc ch 0)
    {
        const float* ip = enc + (size_t)(b * CC) * HW;
        for (int idx = tid; idx < 340; idx += 256) {
            int r = idx / 34, cc2 = idx - r * 34;
            int gy = h0 - 1 + r, gx = w0 - 1 + cc2;
            s_in[0][idx] = (gy >= 0 && gy < HH && gx >= 0 && gx < WW)
                               ? ip[gy * WW + gx] : 0.f;
        }
        for (int idx = tid; idx < 576; idx += 256) s_w[0][idx] = wT[idx];
    }
    __syncthreads();

    const int wglob = w0 + lane;
    const int cxl = (wglob == 0) ? 0 : ((wglob == WW - 1) ? 2 : 1);

    unsigned long long acc2[8][4];
#pragma unroll
    for (int o = 0; o < 8; o++)
#pragma unroll
        for (int m = 0; m < 4; m++) {
            int hA = h0 + 2 * m, hB = hA + 1;
            int cyA = (hA == 0) ? 0 : ((hA == HH - 1) ? 2 : 1);
            int cyB = (hB == 0) ? 0 : ((hB == HH - 1) ? 2 : 1);
            acc2[o][m] = pk2(s_T[(obase + o) * 9 + cyA * 3 + cxl],
                             s_T[(obase + o) * 9 + cyB * 3 + cxl]);
        }

    for (int c = 0; c < 67; c++) {
        const int cur = c & 1, nxt = cur ^ 1;
        const bool has = (c + 1 < 67);
        float tin0 = 0.f, tin1 = 0.f, tw0 = 0.f, tw1 = 0.f, tw2 = 0.f;
        if (has) {
            int cn = c + 1;
            const float* ip = (cn < 64) ? enc + (size_t)(b * CC + cn) * HW
                                        : img + (size_t)(b * 3 + (cn - 64)) * HW;
            {
                int r = tid / 34, cc2 = tid - r * 34;
                int gy = h0 - 1 + r, gx = w0 - 1 + cc2;
                tin0 = (tid < 340 && gy >= 0 && gy < HH && gx >= 0 && gx < WW)
                           ? ip[gy * WW + gx] : 0.f;
            }
            if (tid < 84) {
                int idx = tid + 256;
                int r = idx / 34, cc2 = idx - r * 34;
                int gy = h0 - 1 + r, gx = w0 - 1 + cc2;
                tin1 = (gy >= 0 && gy < HH && gx >= 0 && gx < WW)
                           ? ip[gy * WW + gx] : 0.f;
            }
            const float* wp = wT + (size_t)cn * 576;
            tw0 = wp[tid];
            tw1 = wp[tid + 256];
            if (tid < 64) tw2 = wp[tid + 512];
        }

        const float* si = s_in[cur];
#pragma unroll
        for (int ky = 0; ky < 3; ky++) {
            unsigned long long p2[4][3];
#pragma unroll
            for (int m = 0; m < 4; m++) {
                int r = ky + 2 * m;
#pragma unroll
                for (int k = 0; k < 3; k++)
                    p2[m][k] = pk2(si[r * 34 + lane + k],
                                   si[(r + 1) * 34 + lane + k]);
            }
#pragma unroll
            for (int o = 0; o < 8; o++) {
                const float* ws = &s_w[cur][(obase + o) * 9 + ky * 3];
#pragma unroll
                for (int kx = 0; kx < 3; kx++) {
                    float q = ws[kx];
                    unsigned long long q2 = pk2(q, q);
#pragma unroll
                    for (int m = 0; m < 4; m++) ffma2(acc2[o][m], q2, p2[m][kx]);
                }
            }
        }

        if (has) {
            if (tid < 340) s_in[nxt][tid] = tin0;
            if (tid < 84)  s_in[nxt][tid + 256] = tin1;
            s_w[nxt][tid] = tw0;
            s_w[nxt][tid + 256] = tw1;
            if (tid < 64) s_w[nxt][tid + 512] = tw2;
        }
        __syncthreads();
    }

#pragma unroll
    for (int o = 0; o < 8; o++) {
        int oc = obase + o;
        float s = gg[oc] * rsqrtf(vv[oc] + 1e-5f);
        float t = fmaf(s, bb[oc] - mm[oc], bee[oc]);
#pragma unroll
        for (int m = 0; m < 4; m++) {
            float lo, hi;
            upk2(acc2[o][m], lo, hi);
            float r0 = fmaxf(fmaf(s, lo, t), 0.f);
            float r1 = fmaxf(fmaf(s, hi, t), 0.f);
            size_t base = ((size_t)(b * CC + oc) * HH + (h0 + 2 * m)) * WW + w0 + lane;
            out[base] = r0;
            out[base + WW] = r1;
        }
    }
}

// ---------------- msg contribution T[b][o][case] ---------------------------
__global__ void msgT(const float* __restrict__ msg, const float* __restrict__ wa)
{
    int o = blockIdx.x, b = blockIdx.y, l = threadIdx.x;
    __shared__ float S[9][256];
    float m = msg[b * LL + l];
    const float* wp = wa + ((size_t)o * 323 + l) * 9;
#pragma unroll
    for (int k = 0; k < 9; k++) S[k][l] = m * wp[k];
    __syncthreads();
    for (int s = 128; s > 0; s >>= 1) {
        if (l < s) {
#pragma unroll
            for (int k = 0; k < 9; k++) S[k][l] += S[k][l + s];
        }
        __syncthreads();
    }
    if (l == 0) {
        float P[9];
#pragma unroll
        for (int k = 0; k < 9; k++) P[k] = S[k][0];
        for (int cy = 0; cy < 3; cy++)
            for (int cx = 0; cx < 3; cx++) {
                float t = 0.f;
                for (int ky = 0; ky < 3; ky++) {
                    if (!(cy == 1 || (cy == 0 && ky >= 1) || (cy == 2 && ky <= 1))) continue;
                    for (int kx = 0; kx < 3; kx++) {
                        if (!(cx == 1 || (cx == 0 && kx >= 1) || (cx == 2 && kx <= 1))) continue;
                        t += P[ky * 3 + kx];
                    }
                }
                g_T[((size_t)b * CC + o) * 9 + cy * 3 + cx] = t;
            }
    }
}

// ---------------- watermark: sparse-frequency fft edit ---------------------
__global__ void kG(const float* __restrict__ x)
{
    int h = blockIdx.x, b = blockIdx.y, lane = threadIdx.x;
    __shared__ float ct[256], st[256];
    for (int i = lane; i < 256; i += 32) {
        float s, c;
        sincosf(6.283185307179586f * (float)i / 256.f, &s, &c);
        ct[i] = c; st[i] = s;
    }
    __syncthreads();
    const float* xp = x + ((size_t)(b * CC) * HH + h) * WW;
    float gr[21], gi[21];
#pragma unroll
    for (int j = 0; j < 21; j++) { gr[j] = 0.f; gi[j] = 0.f; }
    for (int w = lane; w < WW; w += 32) {
        float v = xp[w];
#pragma unroll
        for (int j = 0; j < 21; j++) {
            int idx = ((118 + j) * w) & 255;
            gr[j] = fmaf(v, ct[idx], gr[j]);
            gi[j] = fmaf(-v, st[idx], gi[j]);
        }
    }
#pragma unroll
    for (int j = 0; j < 21; j++) {
        for (int off = 16; off; off >>= 1) {
            gr[j] += __shfl_down_sync(0xffffffffu, gr[j], off);
            gi[j] += __shfl_down_sync(0xffffffffu, gi[j], off);
        }
    }
    if (lane == 0) {
#pragma unroll
        for (int j = 0; j < 21; j++)
            g_G[((size_t)b * HH + h) * 21 + j] = make_float2(gr[j], gi[j]);
    }
}

__global__ void kF(const float* __restrict__ msg)
{
    int b = blockIdx.x, l = threadIdx.x;
    __shared__ float ct[256], st[256];
    {
        float s, c;
        sincosf(6.283185307179586f * (float)l / 256.f, &s, &c);
        ct[l] = c; st[l] = s;
    }
    __syncthreads();
    int dy = g_dy[l], dx = g_dx[l];
    int jx = dx + 10, yy = 128 + dy;
    float fr = 0.f, fi = 0.f;
    for (int h = 0; h < HH; h++) {
        float2 G = g_G[((size_t)b * HH + h) * 21 + jx];
        int idx = (yy * h) & 255;
        float c = ct[idx], s = st[idx];
        fr += G.x * c + G.y * s;
        fi += G.y * c - G.x * s;
    }
    float m = msg[b * LL + l];
    g_delta[b * LL + l] = make_float2(m - fr, m - fi);
}

__global__ void kU()
{
    int iy = blockIdx.x, b = blockIdx.y, w = threadIdx.x;
    __shared__ float ct[256], st[256], dr[256], di[256];
    __shared__ int sdx[256], sdy[256];
    {
        float s, c;
        sincosf(6.283185307179586f * (float)w / 256.f, &s, &c);
        ct[w] = c; st[w] = s;
        float2 d = g_delta[b * LL + w];
        dr[w] = d.x; di[w] = d.y;
        sdx[w] = g_dx[w]; sdy[w] = g_dy[w];
    }
    __syncthreads();
    float ur = 0.f, ui = 0.f;
    for (int l = 0; l < LL; l++) {
        if (sdy[l] + 10 == iy) {
            int idx = ((128 + sdx[l]) * w) & 255;
            float c = ct[idx], s = st[idx];
            ur += dr[l] * c - di[l] * s;
            ui += dr[l] * s + di[l] * c;
        }
    }
    g_U[((size_t)b * 21 + iy) * WW + w] = make_float2(ur, ui);
}

__global__ void kAdd(float* __restrict__ x)
{
    int h = blockIdx.x, b = blockIdx.y, w = threadIdx.x;
    __shared__ float ct[256], st[256];
    {
        float s, c;
        sincosf(6.283185307179586f * (float)w / 256.f, &s, &c);
        ct[w] = c; st[w] = s;
    }
    __syncthreads();
    float a = 0.f;
#pragma unroll
    for (int iy = 0; iy < 21; iy++) {
        int idx = ((118 + iy) * h) & 255;
        float2 U = g_U[((size_t)b * 21 + iy) * WW + w];
        a += U.x * ct[idx] - U.y * st[idx];
    }
    size_t off = ((size_t)(b * CC) * HH + h) * WW + w;
    x[off] += a * (1.f / 65536.f);
}

// ---------------- final 1x1 projection 64 -> 3 -----------------------------
__global__ void final1x1(const float* __restrict__ y, const float* __restrict__ wf,
                         const float* __restrict__ bf, float* __restrict__ out)
{
    int w = threadIdx.x, h = blockIdx.x, b = blockIdx.y;
    __shared__ float swf[192];
    __shared__ float sbf[3];
    if (threadIdx.x < 192) swf[threadIdx.x] = wf[threadIdx.x];
    if (threadIdx.x < 3) sbf[threadIdx.x] = bf[threadIdx.x];
    __syncthreads();
    float a0 = sbf[0], a1 = sbf[1], a2 = sbf[2];
    const float* yp = y + ((size_t)(b * CC) * HH + h) * WW + w;
#pragma unroll 8
    for (int c = 0; c < 64; c++) {
        float v = yp[(size_t)c * HW];
        a0 = fmaf(v, swf[c], a0);
        a1 = fmaf(v, swf[64 + c], a1);
        a2 = fmaf(v, swf[128 + c], a2);
    }
    size_t o = ((size_t)(b * 3) * HH + h) * WW + w;
    out[o] = a0;
    out[o + (size_t)HW] = a1;
    out[o + (size_t)2 * HW] = a2;
}

// ---------------- launcher -------------------------------------------------
extern "C" void kernel_launch(void* const* d_in, const int* in_sizes, int n_in,
                              void* d_out, int out_size)
{
    const float* image   = (const float*)d_in[0];
    const float* message = (const float*)d_in[1];
    const float* w0  = (const float*)d_in[2];
    const float* b0  = (const float*)d_in[3];
    const float* g0  = (const float*)d_in[4];
    const float* be0 = (const float*)d_in[5];
    const float* m0  = (const float*)d_in[6];
    const float* v0  = (const float*)d_in[7];
    const float* wk  = (const float*)d_in[8];
    const float* bk  = (const float*)d_in[9];
    const float* gk  = (const float*)d_in[10];
    const float* bek = (const float*)d_in[11];
    const float* mk  = (const float*)d_in[12];
    const float* vk  = (const float*)d_in[13];
    const float* wa  = (const float*)d_in[14];
    const float* ba  = (const float*)d_in[15];
    const float* ga  = (const float*)d_in[16];
    const float* bea = (const float*)d_in[17];
    const float* ma  = (const float*)d_in[18];
    const float* va  = (const float*)d_in[19];
    const float* wf  = (const float*)d_in[20];
    const float* bf  = (const float*)d_in[21];

    float* bufA = nullptr;
    float* bufB = nullptr;
    float* wT = nullptr;
    cudaGetSymbolAddress((void**)&bufA, g_bufA);
    cudaGetSymbolAddress((void**)&bufB, g_bufB);
    cudaGetSymbolAddress((void**)&wT, g_wT);

    const size_t WKS = (size_t)64 * 64 * 9;

    gen_indices<<<1, 1>>>();

    // weight transposes (tiny)
    xposeW<<<7, 256>>>(w0, 3, 0, 3, wT + WT_O0);
    xposeW<<<144, 256>>>(wk, 64, 0, 64, wT + WT_O1);
    xposeW<<<144, 256>>>(wk + WKS, 64, 0, 64, wT + WT_O2);
    xposeW<<<144, 256>>>(wk + 2 * WKS, 64, 0, 64, wT + WT_O3);
    xposeW<<<144, 256>>>(wa, 323, 256, 64, wT + WT_O4);
    xposeW<<<7, 256>>>(wa, 323, 320, 3, wT + WT_O4 + 64 * 576);

    dim3 cgrid(WW / 32, HH / 8, BB);

    conv3x3<<<cgrid, 256>>>(image, 3, wT + WT_O0, b0, g0, be0, m0, v0, bufA);
    conv3x3<<<cgrid, 256>>>(bufA, 64, wT + WT_O1, bk,       gk,       bek,       mk,       vk,       bufB);
    conv3x3<<<cgrid, 256>>>(bufB, 64, wT + WT_O2, bk + 64,  gk + 64,  bek + 64,  mk + 64,  vk + 64,  bufA);
    conv3x3<<<cgrid, 256>>>(bufA, 64, wT + WT_O3, bk + 128, gk + 128, bek + 128, mk + 128, vk + 128, bufB);

    // watermark (modifies channel 0 of bufB in place)
    kG<<<dim3(HH, BB), 32>>>(bufB);
    kF<<<BB, 256>>>(message);
    kU<<<dim3(21, BB), 256>>>();
    kAdd<<<dim3(HH, BB), 256>>>(bufB);

    // message-channel contribution to wa conv
    msgT<<<dim3(64, BB), 256>>>(message, wa);

    conv_wa<<<cgrid, 256>>>(bufB, image, wT + WT_O4, ba, ga, bea, ma, va, bufA);

    final1x1<<<dim3(HH, BB), 256>>>(bufA, wf, bf, (float*)d_out);
}

// round 3
// speedup vs baseline: 1.7063x; 1.0379x over previous
#include <cuda_runtime.h>
#include <cstddef>

// Problem constants
#define HH 256
#define WW 256
#define BB 16
#define CC 64
#define LL 256
#define HW 65536

typedef unsigned long long u64;

// ---------------- scratch (device globals; no allocation allowed) ----------
__device__ float  g_bufA[(size_t)BB * CC * HW];   // 268 MB
__device__ float  g_bufB[(size_t)BB * CC * HW];   // 268 MB
__device__ float2 g_G[(size_t)BB * HH * 21];
__device__ float2 g_delta[BB * LL];
__device__ float2 g_U[(size_t)BB * 21 * WW];
__device__ float  g_T[BB * CC * 9];
__device__ int    g_dy[LL];
__device__ int    g_dx[LL];
// duplicated-pair weights: per channel: 64 oc x 3 ky x 8 floats
// (q0,q0,q1,q1,q2,q2,pad,pad) -> 1536 floats per channel
__device__ float  g_wT2[402432];

#define WT_O0 0
#define WT_O1 4608
#define WT_O2 102912
#define WT_O3 201216
#define WT_O4 299520
#define WT_O4I 397824

// ---------------- f32x2 helpers --------------------------------------------
__device__ __forceinline__ u64 pk2(float lo, float hi) {
    u64 r;
    asm("mov.b64 %0, {%1,%2};" : "=l"(r) : "f"(lo), "f"(hi));
    return r;
}
__device__ __forceinline__ void upk2(u64 v, float& lo, float& hi) {
    asm("mov.b64 {%0,%1}, %2;" : "=f"(lo), "=f"(hi) : "l"(v));
}
__device__ __forceinline__ void ffma2(u64& d, u64 a, u64 b) {
    asm("fma.rn.f32x2 %0, %1, %2, %0;" : "+l"(d) : "l"(a), "l"(b));
}

// ---------------- watermark index generation -------------------------------
__global__ void gen_indices() {
    int n = 0;
    for (int i = -10; i <= 10; i++)
        for (int j = -10; j <= 10; j++)
            if (i * i + j * j <= 100 && n < LL) { g_dy[n] = i; g_dx[n] = j; n++; }
}

// ---------------- weight transpose + duplicate -----------------------------
__global__ void xposeDup(const float* __restrict__ w, int CItot, int cbase, int nc,
                         float* __restrict__ outw) {
    int idx = blockIdx.x * 256 + threadIdx.x;
    if (idx >= nc * 576) return;
    int c = idx / 576, r = idx - c * 576, o = r / 9, j = r - o * 9;
    int ky = j / 3, k = j - ky * 3;
    float v = w[((size_t)o * CItot + cbase + c) * 9 + j];
    size_t base = ((size_t)c * 64 + o) * 24 + ky * 8 + 2 * k;
    outw[base] = v;
    outw[base + 1] = v;
}

// ---------------- conv3x3 + BN + ReLU (column-pair FFMA2) ------------------
// tile 64(w) x 4(h); 256 threads = 8 warps x 8 oc; lane owns column pair
// (w0+2*lane, w0+2*lane+1); 4 rows of f32x2 accumulators per oc.
#define S_STRIDE 68

__global__ void __launch_bounds__(256, 2)
conv3x3(const float* __restrict__ in, int CI, const float* __restrict__ wd,
        const float* __restrict__ bb, const float* __restrict__ gg,
        const float* __restrict__ bee, const float* __restrict__ mm,
        const float* __restrict__ vv, float* __restrict__ out)
{
    const int w0 = blockIdx.x * 64, h0 = blockIdx.y * 4, b = blockIdx.z;
    const int tid = threadIdx.x, lane = tid & 31, wg = tid >> 5;
    const int obase = wg * 8;

    __shared__ __align__(16) float s_in[2][416];   // 6 rows x 66 cols, base off 3, stride 68
    __shared__ __align__(16) float s_wd[2][1536];  // 64 oc x 3 ky x 8 (dup pairs)

    // stage channel 0 into buffer 0
    {
        const float* ip = in + (size_t)(b * CI) * HW;
        for (int idx = tid; idx < 396; idx += 256) {
            int u = idx / 66, xo = idx - u * 66;
            int gy = h0 - 1 + u, gx = w0 - 1 + xo;
            s_in[0][3 + u * S_STRIDE + xo] =
                (gy >= 0 && gy < HH && gx >= 0 && gx < WW) ? ip[gy * WW + gx] : 0.f;
        }
        const float4* wp4 = (const float4*)wd;
        ((float4*)s_wd[0])[tid] = wp4[tid];
        if (tid < 128) ((float4*)s_wd[0])[tid + 256] = wp4[tid + 256];
    }
    __syncthreads();

    u64 acc2[8][4];
#pragma unroll
    for (int o = 0; o < 8; o++)
#pragma unroll
        for (int r = 0; r < 4; r++) acc2[o][r] = 0ull;

    for (int c = 0; c < CI; c++) {
        const int cur = c & 1, nxt = cur ^ 1;
        const bool has = (c + 1 < CI);
        float pin0 = 0.f, pin1 = 0.f;
        float4 pw0, pw1;
        if (has) {
            const float* ip = in + (size_t)(b * CI + c + 1) * HW;
            {
                int u = tid / 66, xo = tid - u * 66;
                int gy = h0 - 1 + u, gx = w0 - 1 + xo;
                pin0 = (gy >= 0 && gy < HH && gx >= 0 && gx < WW) ? ip[gy * WW + gx] : 0.f;
            }
            {
                int idx = tid + 256;
                if (idx < 396) {
                    int u = idx / 66, xo = idx - u * 66;
                    int gy = h0 - 1 + u, gx = w0 - 1 + xo;
                    pin1 = (gy >= 0 && gy < HH && gx >= 0 && gx < WW) ? ip[gy * WW + gx] : 0.f;
                }
            }
            const float4* wp4 = (const float4*)(wd + (size_t)(c + 1) * 1536);
            pw0 = wp4[tid];
            if (tid < 128) pw1 = wp4[tid + 256];
        }

        // build 6 rows x 3 window-pairs in registers
        u64 P[6][3];
        {
            const float* si = s_in[cur] + 3 + 2 * lane;
#pragma unroll
            for (int u = 0; u < 6; u++) {
                const float* rp = si + u * S_STRIDE;
                float f0 = rp[0];
                float2 mmv = *(const float2*)(rp + 1);  // aligned: (3+u*68+2l+1) even
                float f3 = rp[3];
                P[u][0] = pk2(f0, mmv.x);
                P[u][1] = pk2(mmv.x, mmv.y);
                P[u][2] = pk2(mmv.y, f3);
            }
        }

#pragma unroll
        for (int o = 0; o < 8; o++) {
            const float* wb = s_wd[cur] + (obase + o) * 24;
#pragma unroll
            for (int ky = 0; ky < 3; ky++) {
                ulonglong2 wAB = *(const ulonglong2*)(wb + ky * 8);
                u64 wC = *(const u64*)(wb + ky * 8 + 4);
#pragma unroll
                for (int r = 0; r < 4; r++) {
                    int u = r + ky;
                    ffma2(acc2[o][r], wAB.x, P[u][0]);
                    ffma2(acc2[o][r], wAB.y, P[u][1]);
                    ffma2(acc2[o][r], wC,    P[u][2]);
                }
            }
        }

        if (has) {
            {
                int u = tid / 66, xo = tid - u * 66;
                s_in[nxt][3 + u * S_STRIDE + xo] = pin0;
            }
            {
                int idx = tid + 256;
                if (idx < 396) {
                    int u = idx / 66, xo = idx - u * 66;
                    s_in[nxt][3 + u * S_STRIDE + xo] = pin1;
                }
            }
            ((float4*)s_wd[nxt])[tid] = pw0;
            if (tid < 128) ((float4*)s_wd[nxt])[tid + 256] = pw1;
        }
        __syncthreads();
    }

#pragma unroll
    for (int o = 0; o < 8; o++) {
        int oc = obase + o;
        float s = gg[oc] * rsqrtf(vv[oc] + 1e-5f);
        float t = fmaf(s, bb[oc] - mm[oc], bee[oc]);
#pragma unroll
        for (int r = 0; r < 4; r++) {
            float lo, hi;
            upk2(acc2[o][r], lo, hi);
            float2 res;
            res.x = fmaxf(fmaf(s, lo, t), 0.f);
            res.y = fmaxf(fmaf(s, hi, t), 0.f);
            *(float2*)(out + ((size_t)(b * CC + oc) * HH + (h0 + r)) * WW + w0 + 2 * lane) = res;
        }
    }
}

// ---------------- wa conv: 67 effective channels ---------------------------
__global__ void __launch_bounds__(256, 2)
conv_wa(const float* __restrict__ enc, const float* __restrict__ img,
        const float* __restrict__ wd,
        const float* __restrict__ bb, const float* __restrict__ gg,
        const float* __restrict__ bee, const float* __restrict__ mm,
        const float* __restrict__ vv, float* __restrict__ out)
{
    const int w0 = blockIdx.x * 64, h0 = blockIdx.y * 4, b = blockIdx.z;
    const int tid = threadIdx.x, lane = tid & 31, wg = tid >> 5;
    const int obase = wg * 8;

    __shared__ __align__(16) float s_in[2][416];
    __shared__ __align__(16) float s_wd[2][1536];
    __shared__ float s_T[576];

    for (int idx = tid; idx < 576; idx += 256)
        s_T[idx] = g_T[(size_t)b * 576 + idx];

    // stage channel 0 (enc ch 0)
    {
        const float* ip = enc + (size_t)(b * CC) * HW;
        for (int idx = tid; idx < 396; idx += 256) {
            int u = idx / 66, xo = idx - u * 66;
            int gy = h0 - 1 + u, gx = w0 - 1 + xo;
            s_in[0][3 + u * S_STRIDE + xo] =
                (gy >= 0 && gy < HH && gx >= 0 && gx < WW) ? ip[gy * WW + gx] : 0.f;
        }
        const float4* wp4 = (const float4*)wd;
        ((float4*)s_wd[0])[tid] = wp4[tid];
        if (tid < 128) ((float4*)s_wd[0])[tid + 256] = wp4[tid + 256];
    }
    __syncthreads();

    const int colA = w0 + 2 * lane, colB = colA + 1;
    const int cxA = (colA == 0) ? 0 : ((colA == WW - 1) ? 2 : 1);
    const int cxB = (colB == WW - 1) ? 2 : 1;

    u64 acc2[8][4];
#pragma unroll
    for (int o = 0; o < 8; o++)
#pragma unroll
        for (int r = 0; r < 4; r++) {
            int h = h0 + r;
            int cy = (h == 0) ? 0 : ((h == HH - 1) ? 2 : 1);
            const float* Tb = &s_T[(obase + o) * 9 + cy * 3];
            acc2[o][r] = pk2(Tb[cxA], Tb[cxB]);
        }

    for (int c = 0; c < 67; c++) {
        const int cur = c & 1, nxt = cur ^ 1;
        const bool has = (c + 1 < 67);
        float pin0 = 0.f, pin1 = 0.f;
        float4 pw0, pw1;
        if (has) {
            int cn = c + 1;
            const float* ip = (cn < 64) ? enc + (size_t)(b * CC + cn) * HW
                                        : img + (size_t)(b * 3 + (cn - 64)) * HW;
            {
                int u = tid / 66, xo = tid - u * 66;
                int gy = h0 - 1 + u, gx = w0 - 1 + xo;
                pin0 = (gy >= 0 && gy < HH && gx >= 0 && gx < WW) ? ip[gy * WW + gx] : 0.f;
            }
            {
                int idx = tid + 256;
                if (idx < 396) {
                    int u = idx / 66, xo = idx - u * 66;
                    int gy = h0 - 1 + u, gx = w0 - 1 + xo;
                    pin1 = (gy >= 0 && gy < HH && gx >= 0 && gx < WW) ? ip[gy * WW + gx] : 0.f;
                }
            }
            const float4* wp4 = (const float4*)(wd + (size_t)cn * 1536);
            pw0 = wp4[tid];
            if (tid < 128) pw1 = wp4[tid + 256];
        }

        u64 P[6][3];
        {
            const float* si = s_in[cur] + 3 + 2 * lane;
#pragma unroll
            for (int u = 0; u < 6; u++) {
                const float* rp = si + u * S_STRIDE;
                float f0 = rp[0];
                float2 mmv = *(const float2*)(rp + 1);
                float f3 = rp[3];
                P[u][0] = pk2(f0, mmv.x);
                P[u][1] = pk2(mmv.x, mmv.y);
                P[u][2] = pk2(mmv.y, f3);
            }
        }

#pragma unroll
        for (int o = 0; o < 8; o++) {
            const float* wb = s_wd[cur] + (obase + o) * 24;
#pragma unroll
            for (int ky = 0; ky < 3; ky++) {
                ulonglong2 wAB = *(const ulonglong2*)(wb + ky * 8);
                u64 wC = *(const u64*)(wb + ky * 8 + 4);
#pragma unroll
                for (int r = 0; r < 4; r++) {
                    int u = r + ky;
                    ffma2(acc2[o][r], wAB.x, P[u][0]);
                    ffma2(acc2[o][r], wAB.y, P[u][1]);
                    ffma2(acc2[o][r], wC,    P[u][2]);
                }
            }
        }

        if (has) {
            {
                int u = tid / 66, xo = tid - u * 66;
                s_in[nxt][3 + u * S_STRIDE + xo] = pin0;
            }
            {
                int idx = tid + 256;
                if (idx < 396) {
                    int u = idx / 66, xo = idx - u * 66;
                    s_in[nxt][3 + u * S_STRIDE + xo] = pin1;
                }
            }
            ((float4*)s_wd[nxt])[tid] = pw0;
            if (tid < 128) ((float4*)s_wd[nxt])[tid + 256] = pw1;
        }
        __syncthreads();
    }

#pragma unroll
    for (int o = 0; o < 8; o++) {
        int oc = obase + o;
        float s = gg[oc] * rsqrtf(vv[oc] + 1e-5f);
        float t = fmaf(s, bb[oc] - mm[oc], bee[oc]);
#pragma unroll
        for (int r = 0; r < 4; r++) {
            float lo, hi;
            upk2(acc2[o][r], lo, hi);
            float2 res;
            res.x = fmaxf(fmaf(s, lo, t), 0.f);
            res.y = fmaxf(fmaf(s, hi, t), 0.f);
            *(float2*)(out + ((size_t)(b * CC + oc) * HH + (h0 + r)) * WW + w0 + 2 * lane) = res;
        }
    }
}

// ---------------- msg contribution T[b][o][case] ---------------------------
__global__ void msgT(const float* __restrict__ msg, const float* __restrict__ wa)
{
    int o = blockIdx.x, b = blockIdx.y, l = threadIdx.x;
    __shared__ float S[9][256];
    float m = msg[b * LL + l];
    const float* wp = wa + ((size_t)o * 323 + l) * 9;
#pragma unroll
    for (int k = 0; k < 9; k++) S[k][l] = m * wp[k];
    __syncthreads();
    for (int s = 128; s > 0; s >>= 1) {
        if (l < s) {
#pragma unroll
            for (int k = 0; k < 9; k++) S[k][l] += S[k][l + s];
        }
        __syncthreads();
    }
    if (l == 0) {
        float P[9];
#pragma unroll
        for (int k = 0; k < 9; k++) P[k] = S[k][0];
        for (int cy = 0; cy < 3; cy++)
            for (int cx = 0; cx < 3; cx++) {
                float t = 0.f;
                for (int ky = 0; ky < 3; ky++) {
                    if (!(cy == 1 || (cy == 0 && ky >= 1) || (cy == 2 && ky <= 1))) continue;
                    for (int kx = 0; kx < 3; kx++) {
                        if (!(cx == 1 || (cx == 0 && kx >= 1) || (cx == 2 && kx <= 1))) continue;
                        t += P[ky * 3 + kx];
                    }
                }
                g_T[((size_t)b * CC + o) * 9 + cy * 3 + cx] = t;
            }
    }
}

// ---------------- watermark: sparse-frequency fft edit ---------------------
__global__ void kG(const float* __restrict__ x)
{
    int h = blockIdx.x, b = blockIdx.y, lane = threadIdx.x;
    __shared__ float ct[256], st[256];
    for (int i = lane; i < 256; i += 32) {
        float s, c;
        sincosf(6.283185307179586f * (float)i / 256.f, &s, &c);
        ct[i] = c; st[i] = s;
    }
    __syncthreads();
    const float* xp = x + ((size_t)(b * CC) * HH + h) * WW;
    float gr[21], gi[21];
#pragma unroll
    for (int j = 0; j < 21; j++) { gr[j] = 0.f; gi[j] = 0.f; }
    for (int w = lane; w < WW; w += 32) {
        float v = xp[w];
#pragma unroll
        for (int j = 0; j < 21; j++) {
            int idx = ((118 + j) * w) & 255;
            gr[j] = fmaf(v, ct[idx], gr[j]);
            gi[j] = fmaf(-v, st[idx], gi[j]);
        }
    }
#pragma unroll
    for (int j = 0; j < 21; j++) {
        for (int off = 16; off; off >>= 1) {
            gr[j] += __shfl_down_sync(0xffffffffu, gr[j], off);
            gi[j] += __shfl_down_sync(0xffffffffu, gi[j], off);
        }
    }
    if (lane == 0) {
#pragma unroll
        for (int j = 0; j < 21; j++)
            g_G[((size_t)b * HH + h) * 21 + j] = make_float2(gr[j], gi[j]);
    }
}

__global__ void kF(const float* __restrict__ msg)
{
    int b = blockIdx.x, l = threadIdx.x;
    __shared__ float ct[256], st[256];
    {
        float s, c;
        sincosf(6.283185307179586f * (float)l / 256.f, &s, &c);
        ct[l] = c; st[l] = s;
    }
    __syncthreads();
    int dy = g_dy[l], dx = g_dx[l];
    int jx = dx + 10, yy = 128 + dy;
    float fr = 0.f, fi = 0.f;
    for (int h = 0; h < HH; h++) {
        float2 G = g_G[((size_t)b * HH + h) * 21 + jx];
        int idx = (yy * h) & 255;
        float c = ct[idx], s = st[idx];
        fr += G.x * c + G.y * s;
        fi += G.y * c - G.x * s;
    }
    float m = msg[b * LL + l];
    g_delta[b * LL + l] = make_float2(m - fr, m - fi);
}

__global__ void kU()
{
    int iy = blockIdx.x, b = blockIdx.y, w = threadIdx.x;
    __shared__ float ct[256], st[256], dr[256], di[256];
    __shared__ int sdx[256], sdy[256];
    {
        float s, c;
        sincosf(6.283185307179586f * (float)w / 256.f, &s, &c);
        ct[w] = c; st[w] = s;
        float2 d = g_delta[b * LL + w];
        dr[w] = d.x; di[w] = d.y;
        sdx[w] = g_dx[w]; sdy[w] = g_dy[w];
    }
    __syncthreads();
    float ur = 0.f, ui = 0.f;
    for (int l = 0; l < LL; l++) {
        if (sdy[l] + 10 == iy) {
            int idx = ((128 + sdx[l]) * w) & 255;
            float c = ct[idx], s = st[idx];
            ur += dr[l] * c - di[l] * s;
            ui += dr[l] * s + di[l] * c;
        }
    }
    g_U[((size_t)b * 21 + iy) * WW + w] = make_float2(ur, ui);
}

__global__ void kAdd(float* __restrict__ x)
{
    int h = blockIdx.x, b = blockIdx.y, w = threadIdx.x;
    __shared__ float ct[256], st[256];
    {
        float s, c;
        sincosf(6.283185307179586f * (float)w / 256.f, &s, &c);
        ct[w] = c; st[w] = s;
    }
    __syncthreads();
    float a = 0.f;
#pragma unroll
    for (int iy = 0; iy < 21; iy++) {
        int idx = ((118 + iy) * h) & 255;
        float2 U = g_U[((size_t)b * 21 + iy) * WW + w];
        a += U.x * ct[idx] - U.y * st[idx];
    }
    size_t off = ((size_t)(b * CC) * HH + h) * WW + w;
    x[off] += a * (1.f / 65536.f);
}

// ---------------- final 1x1 projection 64 -> 3 -----------------------------
__global__ void final1x1(const float* __restrict__ y, const float* __restrict__ wf,
                         const float* __restrict__ bf, float* __restrict__ out)
{
    int w = threadIdx.x, h = blockIdx.x, b = blockIdx.y;
    __shared__ float swf[192];
    __shared__ float sbf[3];
    if (threadIdx.x < 192) swf[threadIdx.x] = wf[threadIdx.x];
    if (threadIdx.x < 3) sbf[threadIdx.x] = bf[threadIdx.x];
    __syncthreads();
    float a0 = sbf[0], a1 = sbf[1], a2 = sbf[2];
    const float* yp = y + ((size_t)(b * CC) * HH + h) * WW + w;
#pragma unroll 8
    for (int c = 0; c < 64; c++) {
        float v = yp[(size_t)c * HW];
        a0 = fmaf(v, swf[c], a0);
        a1 = fmaf(v, swf[64 + c], a1);
        a2 = fmaf(v, swf[128 + c], a2);
    }
    size_t o = ((size_t)(b * 3) * HH + h) * WW + w;
    out[o] = a0;
    out[o + (size_t)HW] = a1;
    out[o + (size_t)2 * HW] = a2;
}

// ---------------- launcher -------------------------------------------------
extern "C" void kernel_launch(void* const* d_in, const int* in_sizes, int n_in,
                              void* d_out, int out_size)
{
    const float* image   = (const float*)d_in[0];
    const float* message = (const float*)d_in[1];
    const float* w0  = (const float*)d_in[2];
    const float* b0  = (const float*)d_in[3];
    const float* g0  = (const float*)d_in[4];
    const float* be0 = (const float*)d_in[5];
    const float* m0  = (const float*)d_in[6];
    const float* v0  = (const float*)d_in[7];
    const float* wk  = (const float*)d_in[8];
    const float* bk  = (const float*)d_in[9];
    const float* gk  = (const float*)d_in[10];
    const float* bek = (const float*)d_in[11];
    const float* mk  = (const float*)d_in[12];
    const float* vk  = (const float*)d_in[13];
    const float* wa  = (const float*)d_in[14];
    const float* ba  = (const float*)d_in[15];
    const float* ga  = (const float*)d_in[16];
    const float* bea = (const float*)d_in[17];
    const float* ma  = (const float*)d_in[18];
    const float* va  = (const float*)d_in[19];
    const float* wf  = (const float*)d_in[20];
    const float* bf  = (const float*)d_in[21];

    float* bufA = nullptr;
    float* bufB = nullptr;
    float* wT = nullptr;
    cudaGetSymbolAddress((void**)&bufA, g_bufA);
    cudaGetSymbolAddress((void**)&bufB, g_bufB);
    cudaGetSymbolAddress((void**)&wT, g_wT2);

    const size_t WKS = (size_t)64 * 64 * 9;

    gen_indices<<<1, 1>>>();

    // weight transposes into duplicated-pair layout (tiny)
    xposeDup<<<7, 256>>>(w0, 3, 0, 3, wT + WT_O0);
    xposeDup<<<144, 256>>>(wk, 64, 0, 64, wT + WT_O1);
    xposeDup<<<144, 256>>>(wk + WKS, 64, 0, 64, wT + WT_O2);
    xposeDup<<<144, 256>>>(wk + 2 * WKS, 64, 0, 64, wT + WT_O3);
    xposeDup<<<144, 256>>>(wa, 323, 256, 64, wT + WT_O4);
    xposeDup<<<7, 256>>>(wa, 323, 320, 3, wT + WT_O4I);

    dim3 cgrid(WW / 64, HH / 4, BB);

    conv3x3<<<cgrid, 256>>>(image, 3, wT + WT_O0, b0, g0, be0, m0, v0, bufA);
    conv3x3<<<cgrid, 256>>>(bufA, 64, wT + WT_O1, bk,       gk,       bek,       mk,       vk,       bufB);
    conv3x3<<<cgrid, 256>>>(bufB, 64, wT + WT_O2, bk + 64,  gk + 64,  bek + 64,  mk + 64,  vk + 64,  bufA);
    conv3x3<<<cgrid, 256>>>(bufA, 64, wT + WT_O3, bk + 128, gk + 128, bek + 128, mk + 128, vk + 128, bufB);

    // watermark (modifies channel 0 of bufB in place)
    kG<<<dim3(HH, BB), 32>>>(bufB);
    kF<<<BB, 256>>>(message);
    kU<<<dim3(21, BB), 256>>>();
    kAdd<<<dim3(HH, BB), 256>>>(bufB);

    // message-channel contribution to wa conv
    msgT<<<dim3(64, BB), 256>>>(message, wa);

    conv_wa<<<cgrid, 256>>>(bufB, image, wT + WT_O4, ba, ga, bea, ma, va, bufA);

    final1x1<<<dim3(HH, BB), 256>>>(bufA, wf, bf, (float*)d_out);
}